// round 14
// baseline (speedup 1.0000x reference)
#include <cuda_runtime.h>
#include <stdint.h>
#include <limits.h>

// Problem scale (dataset fixed: T=2048, W=30, N=61440, k=819)
#define NMAX  61440
#define TMAX  2048
#define NBK   60          // key-build blocks
#define NT    1024
#define NBIN  65536       // MSD top-16 buckets

#define ST_UND 0
#define ST_ACC 1
#define ST_REJ 2

// ---- device-global scratch (no allocations allowed) ----
__device__ unsigned long long g_bufA[NMAX];     // unsorted keys
__device__ unsigned long long g_bufB[NMAX];     // bucketed/sorted keys
__device__ unsigned int       g_h64[NBIN];      // bucket counts (zeroed by scan each run)
__device__ unsigned int       g_fill64[NBIN];   // exclusive bases -> fill ptrs -> bucket ends

__device__ __forceinline__ bool spans_cross(int s1, int e1, int s2, int e2) {
    return (s1 < s2 && s2 <= e1 && e1 < e2) || (s2 < s1 && s1 <= e2 && e2 < e1);
}

// ============================================================
// 1) keys + top-16 histogram.
// key64 = (~sortable_asc(score+log m)) << 32 | idx  (ascending = ref order)
// ============================================================
__global__ void __launch_bounds__(NT, 1)
k_init(const float* __restrict__ scores, const float* __restrict__ maskp, int N) {
    int i = blockIdx.x * NT + threadIdx.x;
    if (i < N) {
        float key = scores[i] + logf(maskp[i]);
        unsigned b   = __float_as_uint(key);
        unsigned asc = (b & 0x80000000u) ? ~b : (b | 0x80000000u);
        unsigned long long k = ((unsigned long long)(~asc) << 32) | (unsigned)i;
        g_bufA[i] = k;
        atomicAdd(&g_h64[(unsigned)(k >> 48)], 1u);
    }
}

// ============================================================
// 2) exclusive scan of 64K bins -> g_fill64 ; re-zero g_h64 for next replay.
// One block, 1024 threads, 64 contiguous bins each (uint4 I/O).
// ============================================================
__global__ void __launch_bounds__(NT, 1)
k_scan64() {
    __shared__ unsigned wsum[32];
    int t = threadIdx.x, wp = t >> 5, ln = t & 31;
    const unsigned FULL = 0xFFFFFFFFu;

    unsigned v[64];
    {
        const uint4* p = (const uint4*)&g_h64[t * 64];
        #pragma unroll
        for (int j = 0; j < 16; j++) {
            uint4 q = p[j];
            v[4*j] = q.x; v[4*j+1] = q.y; v[4*j+2] = q.z; v[4*j+3] = q.w;
        }
    }
    unsigned S = 0;
    #pragma unroll
    for (int j = 0; j < 64; j++) S += v[j];

    // block exclusive scan of per-thread sums
    unsigned x = S;
    #pragma unroll
    for (int o = 1; o < 32; o <<= 1) {
        unsigned y = __shfl_up_sync(FULL, x, o);
        if (ln >= o) x += y;
    }
    if (ln == 31) wsum[wp] = x;
    __syncthreads();
    if (t < 32) {
        unsigned a = wsum[t], orig = a;
        #pragma unroll
        for (int o = 1; o < 32; o <<= 1) {
            unsigned y = __shfl_up_sync(FULL, a, o);
            if (t >= o) a += y;
        }
        wsum[t] = a - orig;           // exclusive warp bases
    }
    __syncthreads();
    unsigned run = (x - S) + wsum[wp];

    {
        uint4* f = (uint4*)&g_fill64[t * 64];
        uint4* hz = (uint4*)&g_h64[t * 64];
        #pragma unroll
        for (int j = 0; j < 16; j++) {
            uint4 o4;
            o4.x = run; run += v[4*j];
            o4.y = run; run += v[4*j+1];
            o4.z = run; run += v[4*j+2];
            o4.w = run; run += v[4*j+3];
            f[j] = o4;
            hz[j] = make_uint4(0u, 0u, 0u, 0u);   // reset hist for next replay
        }
    }
}

// ============================================================
// 3) scatter into buckets (order within bucket arbitrary; fixup repairs).
// ============================================================
__global__ void __launch_bounds__(NT, 1)
k_scatter64(int N) {
    int i = blockIdx.x * NT + threadIdx.x;
    if (i < N) {
        unsigned long long k = g_bufA[i];
        unsigned pos = atomicAdd(&g_fill64[(unsigned)(k >> 48)], 1u);
        g_bufB[pos] = k;
    }
}

// ============================================================
// 4) fixup: per bucket, insertion-sort by full 64-bit key.
// After scatter, g_fill64[b] = end of bucket b; start = g_fill64[b-1] (or 0).
// ============================================================
__global__ void __launch_bounds__(NT, 1)
k_fixup() {
    int b = blockIdx.x * NT + threadIdx.x;
    if (b >= NBIN) return;
    unsigned lo = (b == 0) ? 0u : __ldg(&g_fill64[b - 1]);
    unsigned hi = __ldg(&g_fill64[b]);
    if (hi - lo < 2u) return;
    for (unsigned a = lo + 1; a < hi; a++) {
        unsigned long long kv = g_bufB[a];
        int c = (int)a - 1;
        while (c >= (int)lo && g_bufB[c] > kv) {
            g_bufB[c + 1] = g_bufB[c];
            c--;
        }
        g_bufB[c + 1] = kv;
    }
}

// ============================================================
// 5) greedy non-crossing selection (block-parallel fixed-point per chunk)
//    + finalize. Bucket entries pack (s<<17 | w<<12 | t<<2 | state):
//    one LDS per scanned entry.
// ============================================================
__global__ void __launch_bounds__(NT, 1)
k_greedy(const int* __restrict__ spans, const float* __restrict__ scores,
         const int* __restrict__ pT, const int* __restrict__ pK,
         int N, float* __restrict__ out, int out_size) {
    __shared__ int s2e[TMAX];                 // start -> max end   (-1 unset)
    __shared__ int e2s[TMAX];                 // end   -> min start (INT_MAX unset)
    __shared__ int bPack[NT];
    __shared__ int bCnt[64], bOff[64], bFill[64];
    __shared__ int wCnt[32], wOff[32];
    __shared__ unsigned long long accList[2048];
    __shared__ int sh_cnt, sh_done;

    const unsigned FULL = 0xFFFFFFFFu;
    int t = threadIdx.x, wp = t >> 5, ln = t & 31;
    unsigned ltm = (1u << ln) - 1u;

    for (int i = t; i < TMAX; i += NT) { s2e[i] = -1; e2s[i] = INT_MAX; }
    if (t == 0) { sh_cnt = 0; sh_done = 0; }
    __syncthreads();

    int T = pT ? pT[0] : TMAX;
    int K = pK ? pK[0] : 819;
    int k_out = out_size / 5;                  // scores,k | idx,k | spans,2k | valid,k
    if (K > NT) K = NT;
    int nch = (N + NT - 1) / NT;

    for (int ch = 0; ch < nch; ch++) {
        if (sh_done) break;
        int cnt0 = sh_cnt;
        int i = ch * NT + t;
        int myState = ST_REJ;
        int s1 = 0, e1 = 0, c1 = 0;
        if (i < N) {
            c1 = (int)(unsigned)(g_bufB[i] & 0xFFFFFFFFull);
            s1 = __ldg(&spans[2 * c1]);
            e1 = __ldg(&spans[2 * c1 + 1]);
            if (s1 == e1) {
                myState = ST_ACC;              // width-0: can never cross
            } else if (cnt0 == 0) {
                myState = ST_UND;
            } else {
                bool cross = false;
                int w = e1 - s1;
                for (int d = 1; d <= w; d++) cross |= (s2e[s1 + d] > e1);
                for (int d = 0; d < w; d++)  cross |= (e2s[s1 + d] < s1);
                myState = cross ? ST_REJ : ST_UND;
            }
        }
        int myB = s1 >> 5;

        // ---- bucket build over UND only ----
        if (t < 64) bCnt[t] = 0;
        __syncthreads();
        if (myState == ST_UND) atomicAdd(&bCnt[myB], 1);
        __syncthreads();
        if (t == 0) {
            int run = 0;
            #pragma unroll
            for (int b = 0; b < 64; b++) { bOff[b] = run; bFill[b] = run; run += bCnt[b]; }
        }
        __syncthreads();
        int myQ = -1, myBase = 0;
        if (myState == ST_UND) {
            myQ = atomicAdd(&bFill[myB], 1);
            myBase = (s1 << 17) | ((e1 - s1) << 12) | (t << 2);
            bPack[myQ] = myBase | ST_UND;
        }
        __syncthreads();

        int bLo = (myB > 0) ? myB - 1 : 0;
        int bHi = (myB < 63) ? myB + 1 : 63;
        int lo = bOff[bLo];
        int hi = bOff[bHi] + bCnt[bHi];

        // ---- rounds: full rescan each round, one LDS per entry ----
        while (true) {
            int und = __syncthreads_count(myState == ST_UND);
            if (und == 0) break;
            if (myState == ST_UND) {
                bool rejected = false, blocked = false;
                for (int q = lo; q < hi && !rejected; q++) {
                    int v = bPack[q];
                    int st = v & 3;
                    int j  = (v >> 2) & 1023;
                    if (st == ST_REJ || j >= t) continue;
                    int s2 = v >> 17;
                    int e2 = s2 + ((v >> 12) & 31);
                    if (spans_cross(s1, e1, s2, e2)) {
                        if (st == ST_ACC) rejected = true;
                        else blocked = true;
                    }
                }
                if (rejected)      { myState = ST_REJ; bPack[myQ] = myBase | ST_REJ; }
                else if (!blocked) { myState = ST_ACC; bPack[myQ] = myBase | ST_ACC; }
            }
        }

        // ---- accepted: update tables for later chunks ----
        bool accd = (myState == ST_ACC);
        if (accd) {
            atomicMax(&s2e[s1], e1);
            atomicMin(&e2s[e1], s1);
        }

        // ---- ordered compaction of accepts -> accList ----
        unsigned bal = __ballot_sync(FULL, accd);
        if (ln == 0) wCnt[wp] = __popc(bal);
        __syncthreads();
        if (t < 32) {
            int vv = wCnt[t], a2 = vv;
            #pragma unroll
            for (int o = 1; o < 32; o <<= 1) {
                int nb = __shfl_up_sync(FULL, a2, o);
                if (t >= o) a2 += nb;
            }
            wOff[t] = a2 - vv;
            if (t == 31) {
                sh_cnt = cnt0 + a2;
                if (cnt0 + a2 >= K) sh_done = 1;
            }
        }
        __syncthreads();
        if (accd) {
            int pos = cnt0 + wOff[wp] + __popc(bal & ltm);
            if (pos < 2048)
                accList[pos] = ((unsigned long long)(s1 * T + e1) << 17) | (unsigned)c1;
        }
        __syncthreads();
    }

    // ---- finalize: first K accepts, bitonic by (s*T+e, idx), emit ----
    int cnt = sh_cnt;
    if (cnt > K) cnt = K;
    if (t >= cnt) accList[t] = 0xFFFFFFFFFFFFFFFFull;
    __syncthreads();

    for (int ks = 2; ks <= NT; ks <<= 1) {
        for (int j = ks >> 1; j > 0; j >>= 1) {
            int ixj = t ^ j;
            if (ixj > t) {
                bool up = ((t & ks) == 0);
                unsigned long long a = accList[t], b = accList[ixj];
                if ((a > b) == up) { accList[t] = b; accList[ixj] = a; }
            }
            __syncthreads();
        }
    }

    int vcnt = (cnt < k_out) ? cnt : k_out;
    for (int j = t; j < k_out; j += NT) {
        bool valid = (j < vcnt);
        int c  = valid ? (int)(accList[j] & 0x1FFFFull) : 0;
        float sc = valid ? scores[c] : 0.0f;
        int ss = valid ? spans[2 * c] : 0;
        int ee = valid ? spans[2 * c + 1] : 0;
        out[j]                     = sc;
        out[k_out + j]             = valid ? (float)c : 0.0f;
        out[2 * k_out + 2 * j]     = (float)ss;
        out[2 * k_out + 2 * j + 1] = (float)ee;
        out[4 * k_out + j]         = valid ? 1.0f : 0.0f;
    }
}

// ============================================================
// Launch: 5 nodes.
// ============================================================
extern "C" void kernel_launch(void* const* d_in, const int* in_sizes, int n_in,
                              void* d_out, int out_size) {
    const int*   spans  = (const int*)d_in[0];
    const float* scores = (const float*)d_in[1];
    const float* mask   = (const float*)d_in[2];
    const int*   pT     = (n_in > 3) ? (const int*)d_in[3] : nullptr;
    const int*   pK     = (n_in > 4) ? (const int*)d_in[4] : nullptr;
    int N = in_sizes[1];

    k_init<<<(N + NT - 1) / NT, NT>>>(scores, mask, N);
    k_scan64<<<1, NT>>>();
    k_scatter64<<<(N + NT - 1) / NT, NT>>>(N);
    k_fixup<<<NBIN / NT, NT>>>();
    k_greedy<<<1, NT>>>(spans, scores, pT, pK, N, (float*)d_out, out_size);
}

// round 16
// speedup vs baseline: 5.4633x; 5.4633x over previous
#include <cuda_runtime.h>
#include <stdint.h>
#include <limits.h>

// Problem scale (dataset fixed: T=2048, W=30, N=61440, k=819)
#define NMAX  61440
#define TMAX  2048
#define NB    60          // radix blocks; NB*CHUNK >= NMAX
#define CHUNK 1024
#define NT    1024

#define ST_UND 0
#define ST_ACC 1
#define ST_REJ 2

// ---- device-global scratch (no allocations allowed) ----
__device__ unsigned long long g_bufA[NMAX];
__device__ unsigned long long g_bufB[NMAX];
__device__ unsigned int       g_hist4[4][256 * NB];
__device__ unsigned int       g_base[NB * 256];   // [block][digit] bases for current pass

__device__ __forceinline__ bool spans_cross(int s1, int e1, int s2, int e2) {
    return (s1 < s2 && s2 <= e1 && e1 < e2) || (s2 < s1 && s1 <= e2 && e2 < e1);
}

// ============================================================
// Kernel 1: keys + pass-0 histogram + zero later-pass histograms.
// key64 = (~sortable_asc(score+log m)) << 32 | idx ; ascending = ref order
// ============================================================
__global__ void __launch_bounds__(CHUNK, 1)
k_init_hist(const float* __restrict__ scores, const float* __restrict__ maskp, int N) {
    __shared__ unsigned h[256];
    int t = threadIdx.x, ln = t & 31;
    unsigned ltm = (1u << ln) - 1u;
    if (t < 256) h[t] = 0;
    __syncthreads();

    int i = blockIdx.x * CHUNK + t;
    bool ok = (i < N);
    unsigned d = 256u + (unsigned)ln;
    if (ok) {
        float key = scores[i] + logf(maskp[i]);
        unsigned b   = __float_as_uint(key);
        unsigned asc = (b & 0x80000000u) ? ~b : (b | 0x80000000u);
        unsigned long long k = ((unsigned long long)(~asc) << 32) | (unsigned)i;
        g_bufA[i] = k;
        d = (unsigned)((k >> 32) & 255u);
    }
    unsigned mm = __match_any_sync(0xFFFFFFFFu, d);
    if (ok && (mm & ltm) == 0u) atomicAdd(&h[d], (unsigned)__popc(mm));
    __syncthreads();

    if (t < 256) {
        g_hist4[0][t * NB + blockIdx.x] = h[t];
        g_hist4[1][t * NB + blockIdx.x] = 0;
        g_hist4[2][t * NB + blockIdx.x] = 0;
        g_hist4[3][t * NB + blockIdx.x] = 0;
    }
}

// ============================================================
// Scan pass p, grid=NB: block b computes ONLY its own base row
// g_base[b*256+d] = scan(digit totals) + prefix of digit d over blocks < b.
// All 60 blocks run concurrently -> wall time = one block's latency.
// ============================================================
__global__ void __launch_bounds__(256, 1)
k_scan(int p) {
    __shared__ unsigned tmp8[8];
    int t = threadIdx.x, wp = t >> 5, ln = t & 31;
    int b = blockIdx.x;
    const unsigned FULL = 0xFFFFFFFFu;
    const unsigned* hp = &g_hist4[p][t * NB];

    unsigned pre = 0, tot = 0;
    #pragma unroll
    for (int bb = 0; bb < NB; bb++) {
        unsigned c = __ldg(&hp[bb]);
        pre += (bb < b) ? c : 0u;
        tot += c;
    }

    // block exclusive scan of per-digit totals
    unsigned x = tot;
    #pragma unroll
    for (int o = 1; o < 32; o <<= 1) {
        unsigned y = __shfl_up_sync(FULL, x, o);
        if (ln >= o) x += y;
    }
    if (ln == 31) tmp8[wp] = x;
    __syncthreads();
    unsigned add = 0;
    #pragma unroll
    for (int w = 0; w < 8; w++) add += (w < wp) ? tmp8[w] : 0u;

    g_base[b * 256 + t] = (x - tot) + add + pre;
}

// ============================================================
// Scatter pass p: 1024 threads, one wave, bases preloaded from g_base.
// Stable match-rank scatter; feeds next pass's per-dest-block hist (p<3).
// ============================================================
__global__ void __launch_bounds__(1024, 1)
k_scatter(int p, int srcIsA, int N) {
    const unsigned long long* src = srcIsA ? g_bufA : g_bufB;
    unsigned long long*       dst = srcIsA ? g_bufB : g_bufA;
    int shift  = 32 + 8 * p;
    int shift2 = shift + 8;

    __shared__ unsigned baseS[256];
    __shared__ unsigned wh[32][257];   // padded: column scan rotates banks
    int t  = threadIdx.x;
    int wp = t >> 5, ln = t & 31;
    unsigned ltm = (1u << ln) - 1u;
    const unsigned FULL = 0xFFFFFFFFu;

    #pragma unroll
    for (int j = t; j < 32 * 257; j += 1024) ((unsigned*)wh)[j] = 0;
    if (t < 256) baseS[t] = __ldg(&g_base[blockIdx.x * 256 + t]);
    __syncthreads();   // zeroing complete before leader count writes

    int i = blockIdx.x * 1024 + t;
    bool ok = (i < N);
    unsigned long long v = ok ? src[i] : 0ull;
    unsigned d = ok ? (unsigned)((v >> shift) & 255u) : (256u + (unsigned)ln);
    unsigned mm = __match_any_sync(FULL, d);
    int lr = __popc(mm & ltm);
    if (ok && lr == 0) wh[wp][d] = (unsigned)__popc(mm);
    __syncthreads();

    if (t < 256) {                      // thread t owns digit t
        unsigned run = baseS[t];
        #pragma unroll
        for (int w = 0; w < 32; w++) { unsigned c = wh[w][t]; wh[w][t] = run; run += c; }
    }
    __syncthreads();

    if (ok) {
        unsigned q = wh[wp][d] + (unsigned)lr;
        dst[q] = v;                                  // stable scatter
        if (p < 3) {
            unsigned d2 = (unsigned)((v >> shift2) & 255u);
            atomicAdd(&g_hist4[p + 1][d2 * NB + (q >> 10)], 1u);
        }
    }
}

// ============================================================
// Greedy non-crossing selection: block-parallel fixed-point per chunk.
//   Prefilter: width-0 -> ACC; reject vs tables (monotone -> final).
//   Rounds (full rescan): ONE LDS per scanned entry — bucket entries pack
//   (s<<17 | w<<12 | t<<2 | state); owner updates its slot's state bits.
// Finalize: first K accepts (candidate order), bitonic by (s*T+e, idx), emit.
// ============================================================
__global__ void __launch_bounds__(NT, 1)
k_greedy(const int* __restrict__ spans, const float* __restrict__ scores,
         const int* __restrict__ pT, const int* __restrict__ pK,
         int N, float* __restrict__ out, int out_size) {
    __shared__ int s2e[TMAX];                 // start -> max end   (-1 unset)
    __shared__ int e2s[TMAX];                 // end   -> min start (INT_MAX unset)
    __shared__ int bPack[NT];
    __shared__ int bCnt[64], bOff[64], bFill[64];
    __shared__ int wCnt[32], wOff[32];
    __shared__ unsigned long long accList[2048];
    __shared__ int sh_cnt, sh_done;

    const unsigned FULL = 0xFFFFFFFFu;
    int t = threadIdx.x, wp = t >> 5, ln = t & 31;
    unsigned ltm = (1u << ln) - 1u;

    for (int i = t; i < TMAX; i += NT) { s2e[i] = -1; e2s[i] = INT_MAX; }
    if (t == 0) { sh_cnt = 0; sh_done = 0; }
    __syncthreads();

    int T = pT ? pT[0] : TMAX;
    int K = pK ? pK[0] : 819;
    int k_out = out_size / 5;                  // scores,k | idx,k | spans,2k | valid,k
    if (K > NT) K = NT;
    int nch = (N + NT - 1) / NT;

    for (int ch = 0; ch < nch; ch++) {
        if (sh_done) break;
        int cnt0 = sh_cnt;
        int i = ch * NT + t;
        int myState = ST_REJ;
        int s1 = 0, e1 = 0, c1 = 0;
        if (i < N) {
            c1 = (int)(unsigned)(g_bufA[i] & 0xFFFFFFFFull);
            s1 = __ldg(&spans[2 * c1]);
            e1 = __ldg(&spans[2 * c1 + 1]);
            if (s1 == e1) {
                myState = ST_ACC;              // width-0: can never cross
            } else if (cnt0 == 0) {
                myState = ST_UND;
            } else {
                bool cross = false;
                int w = e1 - s1;
                for (int d = 1; d <= w; d++) cross |= (s2e[s1 + d] > e1);
                for (int d = 0; d < w; d++)  cross |= (e2s[s1 + d] < s1);
                myState = cross ? ST_REJ : ST_UND;
            }
        }
        int myB = s1 >> 5;

        // ---- bucket build over UND only ----
        if (t < 64) bCnt[t] = 0;
        __syncthreads();
        if (myState == ST_UND) atomicAdd(&bCnt[myB], 1);
        __syncthreads();
        if (t == 0) {
            int run = 0;
            #pragma unroll
            for (int b = 0; b < 64; b++) { bOff[b] = run; bFill[b] = run; run += bCnt[b]; }
        }
        __syncthreads();
        int myQ = -1, myBase = 0;
        if (myState == ST_UND) {
            myQ = atomicAdd(&bFill[myB], 1);
            myBase = (s1 << 17) | ((e1 - s1) << 12) | (t << 2);
            bPack[myQ] = myBase | ST_UND;
        }
        __syncthreads();

        int bLo = (myB > 0) ? myB - 1 : 0;
        int bHi = (myB < 63) ? myB + 1 : 63;
        int lo = bOff[bLo];
        int hi = bOff[bHi] + bCnt[bHi];

        // ---- rounds: full rescan each round, one LDS per entry ----
        while (true) {
            int und = __syncthreads_count(myState == ST_UND);
            if (und == 0) break;
            if (myState == ST_UND) {
                bool rejected = false, blocked = false;
                for (int q = lo; q < hi && !rejected; q++) {
                    int v = bPack[q];
                    int st = v & 3;
                    int j  = (v >> 2) & 1023;
                    if (st == ST_REJ || j >= t) continue;
                    int s2 = v >> 17;
                    int e2 = s2 + ((v >> 12) & 31);
                    if (spans_cross(s1, e1, s2, e2)) {
                        if (st == ST_ACC) rejected = true;
                        else blocked = true;
                    }
                }
                if (rejected)      { myState = ST_REJ; bPack[myQ] = myBase | ST_REJ; }
                else if (!blocked) { myState = ST_ACC; bPack[myQ] = myBase | ST_ACC; }
            }
        }

        // ---- accepted: update tables for later chunks ----
        bool accd = (myState == ST_ACC);
        if (accd) {
            atomicMax(&s2e[s1], e1);
            atomicMin(&e2s[e1], s1);
        }

        // ---- ordered compaction of accepts -> accList ----
        unsigned bal = __ballot_sync(FULL, accd);
        if (ln == 0) wCnt[wp] = __popc(bal);
        __syncthreads();
        if (t < 32) {
            int vv = wCnt[t], a2 = vv;
            #pragma unroll
            for (int o = 1; o < 32; o <<= 1) {
                int nb = __shfl_up_sync(FULL, a2, o);
                if (t >= o) a2 += nb;
            }
            wOff[t] = a2 - vv;
            if (t == 31) {
                sh_cnt = cnt0 + a2;
                if (cnt0 + a2 >= K) sh_done = 1;
            }
        }
        __syncthreads();
        if (accd) {
            int pos = cnt0 + wOff[wp] + __popc(bal & ltm);
            if (pos < 2048)
                accList[pos] = ((unsigned long long)(s1 * T + e1) << 17) | (unsigned)c1;
        }
        __syncthreads();
    }

    // ---- finalize: first K accepts, bitonic by (s*T+e, idx), emit ----
    int cnt = sh_cnt;
    if (cnt > K) cnt = K;
    if (t >= cnt) accList[t] = 0xFFFFFFFFFFFFFFFFull;
    __syncthreads();

    for (int ks = 2; ks <= NT; ks <<= 1) {
        for (int j = ks >> 1; j > 0; j >>= 1) {
            int ixj = t ^ j;
            if (ixj > t) {
                bool up = ((t & ks) == 0);
                unsigned long long a = accList[t], b = accList[ixj];
                if ((a > b) == up) { accList[t] = b; accList[ixj] = a; }
            }
            __syncthreads();
        }
    }

    int vcnt = (cnt < k_out) ? cnt : k_out;
    for (int j = t; j < k_out; j += NT) {
        bool valid = (j < vcnt);
        int c  = valid ? (int)(accList[j] & 0x1FFFFull) : 0;
        float sc = valid ? scores[c] : 0.0f;
        int ss = valid ? spans[2 * c] : 0;
        int ee = valid ? spans[2 * c + 1] : 0;
        out[j]                     = sc;
        out[k_out + j]             = valid ? (float)c : 0.0f;
        out[2 * k_out + 2 * j]     = (float)ss;
        out[2 * k_out + 2 * j + 1] = (float)ee;
        out[4 * k_out + j]         = valid ? 1.0f : 0.0f;
    }
}

// ============================================================
// Launch: 10 nodes.
// ============================================================
extern "C" void kernel_launch(void* const* d_in, const int* in_sizes, int n_in,
                              void* d_out, int out_size) {
    const int*   spans  = (const int*)d_in[0];
    const float* scores = (const float*)d_in[1];
    const float* mask   = (const float*)d_in[2];
    const int*   pT     = (n_in > 3) ? (const int*)d_in[3] : nullptr;
    const int*   pK     = (n_in > 4) ? (const int*)d_in[4] : nullptr;
    int N = in_sizes[1];

    k_init_hist<<<NB, CHUNK>>>(scores, mask, N);
    k_scan<<<NB, 256>>>(0);
    k_scatter<<<NB, 1024>>>(0, 1, N);   // A -> B
    k_scan<<<NB, 256>>>(1);
    k_scatter<<<NB, 1024>>>(1, 0, N);   // B -> A
    k_scan<<<NB, 256>>>(2);
    k_scatter<<<NB, 1024>>>(2, 1, N);   // A -> B
    k_scan<<<NB, 256>>>(3);
    k_scatter<<<NB, 1024>>>(3, 0, N);   // B -> A  (sorted in g_bufA)
    k_greedy<<<1, NT>>>(spans, scores, pT, pK, N, (float*)d_out, out_size);
}

// round 17
// speedup vs baseline: 6.4798x; 1.1861x over previous
#include <cuda_runtime.h>
#include <stdint.h>
#include <limits.h>

// Problem scale (dataset fixed: T=2048, W=30, N=61440, k=819)
#define NMAX  61440
#define TMAX  2048
#define NB    60          // radix blocks; NB*CHUNK >= NMAX
#define CHUNK 1024
#define NT    1024

#define ST_UND 0
#define ST_ACC 1
#define ST_REJ 2

// ---- device-global scratch (no allocations allowed) ----
// g_hist4 layout: [pass][block*256 + digit]  (coalesced for init stores + scan loads)
__device__ unsigned long long g_bufA[NMAX];
__device__ unsigned long long g_bufB[NMAX];
__device__ unsigned int       g_hist4[4][NB * 256];
__device__ unsigned int       g_base[NB * 256];   // [block*256 + digit] bases

__device__ __forceinline__ bool spans_cross(int s1, int e1, int s2, int e2) {
    return (s1 < s2 && s2 <= e1 && e1 < e2) || (s2 < s1 && s1 <= e2 && e2 < e1);
}

// ============================================================
// Kernel 1: keys + pass-0 histogram + zero later-pass histograms.
// key64 = (~sortable_asc(score+log m)) << 32 | idx ; ascending = ref order
// ============================================================
__global__ void __launch_bounds__(CHUNK, 1)
k_init_hist(const float* __restrict__ scores, const float* __restrict__ maskp, int N) {
    __shared__ unsigned h[256];
    int t = threadIdx.x, ln = t & 31;
    unsigned ltm = (1u << ln) - 1u;
    if (t < 256) h[t] = 0;
    __syncthreads();

    int i = blockIdx.x * CHUNK + t;
    bool ok = (i < N);
    unsigned d = 256u + (unsigned)ln;
    if (ok) {
        float key = scores[i] + logf(maskp[i]);
        unsigned b   = __float_as_uint(key);
        unsigned asc = (b & 0x80000000u) ? ~b : (b | 0x80000000u);
        unsigned long long k = ((unsigned long long)(~asc) << 32) | (unsigned)i;
        g_bufA[i] = k;
        d = (unsigned)((k >> 32) & 255u);
    }
    unsigned mm = __match_any_sync(0xFFFFFFFFu, d);
    if (ok && (mm & ltm) == 0u) atomicAdd(&h[d], (unsigned)__popc(mm));
    __syncthreads();

    if (t < 256) {                                   // coalesced stores
        int o = blockIdx.x * 256 + t;
        g_hist4[0][o] = h[t];
        g_hist4[1][o] = 0;
        g_hist4[2][o] = 0;
        g_hist4[3][o] = 0;
    }
}

// ============================================================
// Scan pass p, grid=NB: block b computes only its own base row.
// Loads g_hist4[p][bb*256 + t] -> coalesced per bb iteration.
// ============================================================
__global__ void __launch_bounds__(256, 1)
k_scan(int p) {
    __shared__ unsigned tmp8[8];
    int t = threadIdx.x, wp = t >> 5, ln = t & 31;
    int b = blockIdx.x;
    const unsigned FULL = 0xFFFFFFFFu;

    unsigned pre = 0, tot = 0;
    #pragma unroll
    for (int bb = 0; bb < NB; bb++) {
        unsigned c = __ldg(&g_hist4[p][bb * 256 + t]);
        pre += (bb < b) ? c : 0u;
        tot += c;
    }

    // block exclusive scan of per-digit totals
    unsigned x = tot;
    #pragma unroll
    for (int o = 1; o < 32; o <<= 1) {
        unsigned y = __shfl_up_sync(FULL, x, o);
        if (ln >= o) x += y;
    }
    if (ln == 31) tmp8[wp] = x;
    __syncthreads();
    unsigned add = 0;
    #pragma unroll
    for (int w = 0; w < 8; w++) add += (w < wp) ? tmp8[w] : 0u;

    g_base[b * 256 + t] = (x - tot) + add + pre;
}

// ============================================================
// Scatter pass p: 1024 threads, one wave, bases preloaded from g_base.
// Stable match-rank scatter; feeds next pass's per-dest-block hist (p<3).
// ============================================================
__global__ void __launch_bounds__(1024, 1)
k_scatter(int p, int srcIsA, int N) {
    const unsigned long long* src = srcIsA ? g_bufA : g_bufB;
    unsigned long long*       dst = srcIsA ? g_bufB : g_bufA;
    int shift  = 32 + 8 * p;
    int shift2 = shift + 8;

    __shared__ unsigned baseS[256];
    __shared__ unsigned wh[32][257];   // padded: column scan rotates banks
    int t  = threadIdx.x;
    int wp = t >> 5, ln = t & 31;
    unsigned ltm = (1u << ln) - 1u;
    const unsigned FULL = 0xFFFFFFFFu;

    #pragma unroll
    for (int j = t; j < 32 * 257; j += 1024) ((unsigned*)wh)[j] = 0;
    if (t < 256) baseS[t] = __ldg(&g_base[blockIdx.x * 256 + t]);
    __syncthreads();   // zeroing complete before leader count writes

    int i = blockIdx.x * 1024 + t;
    bool ok = (i < N);
    unsigned long long v = ok ? src[i] : 0ull;
    unsigned d = ok ? (unsigned)((v >> shift) & 255u) : (256u + (unsigned)ln);
    unsigned mm = __match_any_sync(FULL, d);
    int lr = __popc(mm & ltm);
    if (ok && lr == 0) wh[wp][d] = (unsigned)__popc(mm);
    __syncthreads();

    if (t < 256) {                      // thread t owns digit t
        unsigned run = baseS[t];
        #pragma unroll
        for (int w = 0; w < 32; w++) { unsigned c = wh[w][t]; wh[w][t] = run; run += c; }
    }
    __syncthreads();

    if (ok) {
        unsigned q = wh[wp][d] + (unsigned)lr;
        dst[q] = v;                                  // stable scatter
        if (p < 3) {
            unsigned d2 = (unsigned)((v >> shift2) & 255u);
            atomicAdd(&g_hist4[p + 1][(q >> 10) * 256 + d2], 1u);
        }
    }
}

// ============================================================
// Greedy non-crossing selection: block-parallel fixed-point per chunk.
//   Prefilter: width-0 -> ACC; reject vs PACKED table (one LDS/token):
//     pk[i] = (s2e[i]+1)<<16 | min(e2s[i],0xFFFF), rebuilt at chunk start.
//   Rounds (full rescan): one LDS per entry via bPack
//     (s<<17 | w<<12 | t<<2 | state).
// Finalize: first K accepts, bitonic by (s*T+e, idx), emit.
// ============================================================
__global__ void __launch_bounds__(NT, 1)
k_greedy(const int* __restrict__ spans, const float* __restrict__ scores,
         const int* __restrict__ pT, const int* __restrict__ pK,
         int N, float* __restrict__ out, int out_size) {
    __shared__ int s2e[TMAX];                 // start -> max end   (-1 unset)
    __shared__ int e2s[TMAX];                 // end   -> min start (INT_MAX unset)
    __shared__ int pk[TMAX];                  // packed prefilter table
    __shared__ int bPack[NT];
    __shared__ int bCnt[64], bOff[64], bFill[64];
    __shared__ int wCnt[32], wOff[32];
    __shared__ unsigned long long accList[2048];
    __shared__ int sh_cnt, sh_done;

    const unsigned FULL = 0xFFFFFFFFu;
    int t = threadIdx.x, wp = t >> 5, ln = t & 31;
    unsigned ltm = (1u << ln) - 1u;

    for (int i = t; i < TMAX; i += NT) { s2e[i] = -1; e2s[i] = INT_MAX; }
    if (t == 0) { sh_cnt = 0; sh_done = 0; }
    __syncthreads();

    int T = pT ? pT[0] : TMAX;
    int K = pK ? pK[0] : 819;
    int k_out = out_size / 5;                  // scores,k | idx,k | spans,2k | valid,k
    if (K > NT) K = NT;
    int nch = (N + NT - 1) / NT;
    const int2* sp2 = (const int2*)spans;

    for (int ch = 0; ch < nch; ch++) {
        if (sh_done) break;
        int cnt0 = sh_cnt;

        // rebuild packed prefilter table (only needed once tables are nonempty)
        if (cnt0 > 0) {
            for (int i = t; i < TMAX; i += NT) {
                int a = s2e[i];
                int b2 = e2s[i];
                pk[i] = ((a + 1) << 16) | (b2 > 0xFFFF ? 0xFFFF : b2);
            }
            __syncthreads();
        }

        int i = ch * NT + t;
        int myState = ST_REJ;
        int s1 = 0, e1 = 0, c1 = 0;
        if (i < N) {
            c1 = (int)(unsigned)(g_bufA[i] & 0xFFFFFFFFull);
            int2 se = __ldg(&sp2[c1]);
            s1 = se.x; e1 = se.y;
            if (s1 == e1) {
                myState = ST_ACC;              // width-0: can never cross
            } else if (cnt0 == 0) {
                myState = ST_UND;
            } else {
                bool cross = false;
                int w = e1 - s1;
                int ep1 = e1 + 1;
                for (int d = 0; d <= w; d++) {
                    int v = pk[s1 + d];
                    if (d >= 1) cross |= ((v >> 16) > ep1);          // s2e > e1
                    if (d < w)  cross |= ((v & 0xFFFF) < s1);        // e2s < s1
                }
                myState = cross ? ST_REJ : ST_UND;
            }
        }
        int myB = s1 >> 5;

        // ---- bucket build over UND only ----
        if (t < 64) bCnt[t] = 0;
        __syncthreads();
        if (myState == ST_UND) atomicAdd(&bCnt[myB], 1);
        __syncthreads();
        if (t == 0) {
            int run = 0;
            #pragma unroll
            for (int b = 0; b < 64; b++) { bOff[b] = run; bFill[b] = run; run += bCnt[b]; }
        }
        __syncthreads();
        int myQ = -1, myBase = 0;
        if (myState == ST_UND) {
            myQ = atomicAdd(&bFill[myB], 1);
            myBase = (s1 << 17) | ((e1 - s1) << 12) | (t << 2);
            bPack[myQ] = myBase | ST_UND;
        }
        __syncthreads();

        int bLo = (myB > 0) ? myB - 1 : 0;
        int bHi = (myB < 63) ? myB + 1 : 63;
        int lo = bOff[bLo];
        int hi = bOff[bHi] + bCnt[bHi];

        // ---- rounds: full rescan each round, one LDS per entry ----
        while (true) {
            int und = __syncthreads_count(myState == ST_UND);
            if (und == 0) break;
            if (myState == ST_UND) {
                bool rejected = false, blocked = false;
                for (int q = lo; q < hi && !rejected; q++) {
                    int v = bPack[q];
                    int st = v & 3;
                    int j  = (v >> 2) & 1023;
                    if (st == ST_REJ || j >= t) continue;
                    int s2 = v >> 17;
                    int e2 = s2 + ((v >> 12) & 31);
                    if (spans_cross(s1, e1, s2, e2)) {
                        if (st == ST_ACC) rejected = true;
                        else blocked = true;
                    }
                }
                if (rejected)      { myState = ST_REJ; bPack[myQ] = myBase | ST_REJ; }
                else if (!blocked) { myState = ST_ACC; bPack[myQ] = myBase | ST_ACC; }
            }
        }

        // ---- accepted: update tables for later chunks ----
        bool accd = (myState == ST_ACC);
        if (accd) {
            atomicMax(&s2e[s1], e1);
            atomicMin(&e2s[e1], s1);
        }

        // ---- ordered compaction of accepts -> accList ----
        unsigned bal = __ballot_sync(FULL, accd);
        if (ln == 0) wCnt[wp] = __popc(bal);
        __syncthreads();
        if (t < 32) {
            int vv = wCnt[t], a2 = vv;
            #pragma unroll
            for (int o = 1; o < 32; o <<= 1) {
                int nb = __shfl_up_sync(FULL, a2, o);
                if (t >= o) a2 += nb;
            }
            wOff[t] = a2 - vv;
            if (t == 31) {
                sh_cnt = cnt0 + a2;
                if (cnt0 + a2 >= K) sh_done = 1;
            }
        }
        __syncthreads();
        if (accd) {
            int pos = cnt0 + wOff[wp] + __popc(bal & ltm);
            if (pos < 2048)
                accList[pos] = ((unsigned long long)(s1 * T + e1) << 17) | (unsigned)c1;
        }
        __syncthreads();
    }

    // ---- finalize: first K accepts, bitonic by (s*T+e, idx), emit ----
    int cnt = sh_cnt;
    if (cnt > K) cnt = K;
    if (t >= cnt) accList[t] = 0xFFFFFFFFFFFFFFFFull;
    __syncthreads();

    for (int ks = 2; ks <= NT; ks <<= 1) {
        for (int j = ks >> 1; j > 0; j >>= 1) {
            int ixj = t ^ j;
            if (ixj > t) {
                bool up = ((t & ks) == 0);
                unsigned long long a = accList[t], b = accList[ixj];
                if ((a > b) == up) { accList[t] = b; accList[ixj] = a; }
            }
            __syncthreads();
        }
    }

    int vcnt = (cnt < k_out) ? cnt : k_out;
    for (int j = t; j < k_out; j += NT) {
        bool valid = (j < vcnt);
        int c  = valid ? (int)(accList[j] & 0x1FFFFull) : 0;
        float sc = valid ? scores[c] : 0.0f;
        int ss = valid ? spans[2 * c] : 0;
        int ee = valid ? spans[2 * c + 1] : 0;
        out[j]                     = sc;
        out[k_out + j]             = valid ? (float)c : 0.0f;
        out[2 * k_out + 2 * j]     = (float)ss;
        out[2 * k_out + 2 * j + 1] = (float)ee;
        out[4 * k_out + j]         = valid ? 1.0f : 0.0f;
    }
}

// ============================================================
// Launch: 10 nodes.
// ============================================================
extern "C" void kernel_launch(void* const* d_in, const int* in_sizes, int n_in,
                              void* d_out, int out_size) {
    const int*   spans  = (const int*)d_in[0];
    const float* scores = (const float*)d_in[1];
    const float* mask   = (const float*)d_in[2];
    const int*   pT     = (n_in > 3) ? (const int*)d_in[3] : nullptr;
    const int*   pK     = (n_in > 4) ? (const int*)d_in[4] : nullptr;
    int N = in_sizes[1];

    k_init_hist<<<NB, CHUNK>>>(scores, mask, N);
    k_scan<<<NB, 256>>>(0);
    k_scatter<<<NB, 1024>>>(0, 1, N);   // A -> B
    k_scan<<<NB, 256>>>(1);
    k_scatter<<<NB, 1024>>>(1, 0, N);   // B -> A
    k_scan<<<NB, 256>>>(2);
    k_scatter<<<NB, 1024>>>(2, 1, N);   // A -> B
    k_scan<<<NB, 256>>>(3);
    k_scatter<<<NB, 1024>>>(3, 0, N);   // B -> A  (sorted in g_bufA)
    k_greedy<<<1, NT>>>(spans, scores, pT, pK, N, (float*)d_out, out_size);
}